// round 17
// baseline (speedup 1.0000x reference)
#include <cuda_runtime.h>
#include <math.h>

// LanczosUpsampling: (4,2,256,256) f32 -> (4,2,2048,2048), exact 8x separable lanczos(a=4).
//
// With scale exactly 8 there are only 8 fractional phases, and each phase's 9 taps
// span at most 2 source samples per axis. Separable form:
//   out[8rb+fy, 8cb+fx] = wy{l,r}[fy] (x) wx{l,r}[fx] applied to a 2x2 source patch,
// where fy<=3 uses rows (rb-1, rb), fy>=4 uses (rb, rb+1) (same for columns),
// and reflect padding reduces exactly to index clamping.
//
// One thread produces a 4-wide x 8-tall output patch (32 px): 6 scalar source loads,
// horizontal pass per source row, then 8 vertical combines + 8 coalesced STG.128.
// R15 measured .cs (evict-first) at 23.3us total. This round: .wt (write-through)
// stores — avoid dirty-L2 accumulation entirely so no post-kernel drain remains.
// Weights (128 B) are host-computed, passed by value (const bank).

namespace {
constexpr int HS = 256;
constexpr int WS = 256;
constexpr int HO = 2048;
constexpr int NIMG = 8;      // B*C
constexpr int RBLK = HO / 8; // 256 source row blocks per image
}

struct LzW {
    float wxl[8], wxr[8];  // horizontal left/right aggregated tap sums per phase
    float wyl[8], wyr[8];  // vertical
};

__global__ __launch_bounds__(256)
void lz_main_kernel(const float* __restrict__ img, float* __restrict__ out, LzW W) {
    const unsigned tid = blockIdx.x * 256u + threadIdx.x;
    const int j4   = tid & 511;           // float4 slot within an output row
    const int rb   = (tid >> 9) & 255;    // source row block (8 output rows)
    const int bc   = tid >> 17;           // image index (B*C)
    const int half = j4 & 1;              // 0 -> col phases 0..3, 1 -> 4..7
    const int cb   = j4 >> 1;             // source column block

    const int cA = half ? cb : max(cb - 1, 0);
    const int cB = half ? min(cb + 1, WS - 1) : cb;
    const int rT = max(rb - 1, 0);
    const int rB = min(rb + 1, HS - 1);

    const float* __restrict__ base = img + (size_t)bc * (HS * WS);
    const float vTA = __ldg(base + rT * WS + cA);
    const float vTB = __ldg(base + rT * WS + cB);
    const float vMA = __ldg(base + rb * WS + cA);
    const float vMB = __ldg(base + rb * WS + cB);
    const float vBA = __ldg(base + rB * WS + cA);
    const float vBB = __ldg(base + rB * WS + cB);

    // Horizontal pass for each of the three source rows (4 column phases each).
    float hT[4], hM[4], hB[4];
    #pragma unroll
    for (int k = 0; k < 4; ++k) {
        const float wl = half ? W.wxl[k + 4] : W.wxl[k];
        const float wr = half ? W.wxr[k + 4] : W.wxr[k];
        hT[k] = wl * vTA + wr * vTB;
        hM[k] = wl * vMA + wr * vMB;
        hB[k] = wl * vBA + wr * vBB;
    }

    // Vertical pass: 8 output rows, each a coalesced write-through float4 store.
    float4* __restrict__ orow =
        reinterpret_cast<float4*>(out) + ((size_t)bc * HO + (size_t)rb * 8) * 512 + j4;
    #pragma unroll
    for (int fy = 0; fy < 8; ++fy) {
        const float wl = W.wyl[fy];
        const float wr = W.wyr[fy];
        const float* hA = (fy < 4) ? hT : hM;   // resolved at compile time (unrolled)
        const float* hC = (fy < 4) ? hM : hB;
        float4 o;
        o.x = wl * hA[0] + wr * hC[0];
        o.y = wl * hA[1] + wr * hC[1];
        o.z = wl * hA[2] + wr * hC[2];
        o.w = wl * hA[3] + wr * hC[3];
        __stwt(orow + (size_t)fy * 512, o);     // st.global.wt.v4.f32 (write-through)
    }
}

extern "C" void kernel_launch(void* const* d_in, const int* in_sizes, int n_in,
                              void* d_out, int out_size) {
    (void)in_sizes; (void)n_in; (void)out_size;
    const float* img = (const float*)d_in[0];
    float* out = (float*)d_out;

    // Host-side weight computation (pure constants; deterministic every call).
    LzW W;
    const double pi = 3.14159265358979323846;
    for (int f = 0; f < 8; ++f) {
        const double delta = 1e-8 + f / 8.0;
        const int s = (f <= 3) ? (4 - f) : (12 - f);  // taps p < s hit the left source sample
        double wl = 0.0, wr = 0.0;
        for (int p = 0; p < 9; ++p) {
            const double x = delta + (double)(p - 4);
            const double a = x * pi;
            const double b = a * 0.25;  // lanczos a = 4
            const double w = (sin(a) / a) * (sin(b) / b);
            if (p < s) wl += w; else wr += w;
        }
        W.wxl[f] = (float)wl;  W.wxr[f] = (float)wr;
        W.wyl[f] = (float)wl;  W.wyr[f] = (float)wr;
    }

    // 8 images * 256 row-blocks * 512 float4-columns = 1,048,576 threads, 32 px each.
    const unsigned total_threads = (unsigned)NIMG * RBLK * 512;
    lz_main_kernel<<<total_threads / 256, 256>>>(img, out, W);
}